// round 2
// baseline (speedup 1.0000x reference)
#include <cuda_runtime.h>
#include <math.h>

#define BSZ    4
#define LEN    4096
#define DMODEL 1024
#define DIN    2048
#define NH     32
#define HD     64
#define DST    32
#define NPROJ  4192
#define NC     64
#define NROWS  16384   // BSZ*LEN

// ---------------- scratch (device globals; no allocation allowed) ----------------
__device__ float g_h[NROWS * DMODEL];          // post-layernorm
__device__ float g_zx[NROWS * NPROJ];          // in_proj output
__device__ float g_xh[NROWS * DIN];            // silu(x-part)
__device__ float g_dt[NROWS * NH];             // softplus dt
__device__ float g_a[NROWS * NH];              // dt * A  (negative)
__device__ float g_Bcq[NROWS * DST];           // silu+rope B
__device__ float g_Ccq[NROWS * DST];           // silu+rope C
__device__ float g_scores[BSZ * NC * 64 * 64]; // C·B^T per (b,chunk)
__device__ float g_acs[BSZ * NC * NH * 64];    // per-chunk inclusive cumsum of a
__device__ float g_S[BSZ * NC * NH * HD * DST];   // local chunk states
__device__ float g_Sin[BSZ * NC * NH * HD * DST]; // carried-in states
__device__ float g_y[NROWS * DIN];             // SSD output
__device__ float g_yn[NROWS * DIN];            // gated+rmsnormed

__device__ __forceinline__ float siluf(float v) { return v / (1.f + expf(-v)); }

__device__ __forceinline__ float blk_reduce(float v, float* sb) {
    #pragma unroll
    for (int o = 16; o > 0; o >>= 1) v += __shfl_down_sync(0xffffffffu, v, o);
    int lane = threadIdx.x & 31, w = threadIdx.x >> 5;
    if (lane == 0) sb[w] = v;
    __syncthreads();
    if (threadIdx.x < 32) {
        v = (threadIdx.x < (blockDim.x >> 5)) ? sb[threadIdx.x] : 0.f;
        #pragma unroll
        for (int o = 4; o > 0; o >>= 1) v += __shfl_down_sync(0xffffffffu, v, o);
        if (threadIdx.x == 0) sb[0] = v;
    }
    __syncthreads();
    float r = sb[0];
    __syncthreads();
    return r;
}

// ---------------- 1. LayerNorm ----------------
__global__ __launch_bounds__(256) void layernorm_kernel(
    const float* __restrict__ x, const float* __restrict__ w, const float* __restrict__ b)
{
    __shared__ float sb[32];
    int r = blockIdx.x, tid = threadIdx.x;
    const float* xr = x + (size_t)r * DMODEL;
    float v[4], s = 0.f, sq = 0.f;
    #pragma unroll
    for (int k = 0; k < 4; k++) { int i = tid + k * 256; v[k] = xr[i]; s += v[k]; sq += v[k] * v[k]; }
    s  = blk_reduce(s, sb);
    sq = blk_reduce(sq, sb);
    float mean = s * (1.f / DMODEL);
    float var  = sq * (1.f / DMODEL) - mean * mean;
    float inv  = rsqrtf(var + 1e-6f);
    float* hr = g_h + (size_t)r * DMODEL;
    #pragma unroll
    for (int k = 0; k < 4; k++) { int i = tid + k * 256; hr[i] = (v[k] - mean) * inv * w[i] + b[i]; }
}

// ---------------- generic SGEMM: Cout = A@B (+Cadd), A[M,K] B[K,N] row-major ----------------
__global__ __launch_bounds__(256) void sgemm_kernel(
    const float* __restrict__ A, const float* __restrict__ B,
    const float* __restrict__ Cadd, float* __restrict__ Cout,
    int M, int N, int K)
{
    __shared__ float As[8][128];
    __shared__ float Bs[8][128];
    const int tid = threadIdx.x;
    const int bm = blockIdx.y * 128;
    const int bn = blockIdx.x * 128;
    const int trow = (tid >> 4) << 3;
    const int tcol = (tid & 15) << 3;
    const int arow = tid >> 1;
    const int acol = (tid & 1) << 2;
    const int brow = tid >> 5;
    const int bcol = (tid & 31) << 2;
    float acc[8][8];
    #pragma unroll
    for (int i = 0; i < 8; i++)
        #pragma unroll
        for (int j = 0; j < 8; j++) acc[i][j] = 0.f;
    const bool bok = (bn + bcol) < N;
    for (int k0 = 0; k0 < K; k0 += 8) {
        float4 av = *reinterpret_cast<const float4*>(A + (size_t)(bm + arow) * K + k0 + acol);
        As[acol + 0][arow] = av.x; As[acol + 1][arow] = av.y;
        As[acol + 2][arow] = av.z; As[acol + 3][arow] = av.w;
        float4 bv = make_float4(0.f, 0.f, 0.f, 0.f);
        if (bok) bv = *reinterpret_cast<const float4*>(B + (size_t)(k0 + brow) * N + bn + bcol);
        *reinterpret_cast<float4*>(&Bs[brow][bcol]) = bv;
        __syncthreads();
        #pragma unroll
        for (int kk = 0; kk < 8; kk++) {
            float4 a0 = *reinterpret_cast<const float4*>(&As[kk][trow]);
            float4 a1 = *reinterpret_cast<const float4*>(&As[kk][trow + 4]);
            float4 b0 = *reinterpret_cast<const float4*>(&Bs[kk][tcol]);
            float4 b1 = *reinterpret_cast<const float4*>(&Bs[kk][tcol + 4]);
            float ar[8] = {a0.x, a0.y, a0.z, a0.w, a1.x, a1.y, a1.z, a1.w};
            float br[8] = {b0.x, b0.y, b0.z, b0.w, b1.x, b1.y, b1.z, b1.w};
            #pragma unroll
            for (int i = 0; i < 8; i++)
                #pragma unroll
                for (int j = 0; j < 8; j++) acc[i][j] = fmaf(ar[i], br[j], acc[i][j]);
        }
        __syncthreads();
    }
    #pragma unroll
    for (int i = 0; i < 8; i++) {
        int m = bm + trow + i;
        #pragma unroll
        for (int j = 0; j < 8; j += 4) {
            int n = bn + tcol + j;
            if (n < N) {
                float4 v = make_float4(acc[i][j], acc[i][j + 1], acc[i][j + 2], acc[i][j + 3]);
                if (Cadd) {
                    float4 cv = *reinterpret_cast<const float4*>(Cadd + (size_t)m * N + n);
                    v.x += cv.x; v.y += cv.y; v.z += cv.z; v.w += cv.w;
                }
                *reinterpret_cast<float4*>(Cout + (size_t)m * N + n) = v;
            }
        }
    }
}

// ---------------- 3. split + silu + softplus + rope ----------------
__global__ __launch_bounds__(256) void prep_kernel(
    const float* __restrict__ dt_bias, const float* __restrict__ A_log)
{
    int r = blockIdx.x, tid = threadIdx.x;
    int l = r & (LEN - 1);
    const float* row = g_zx + (size_t)r * NPROJ;
    __shared__ float sB[DST], sC[DST];
    #pragma unroll
    for (int k = 0; k < 8; k++) {
        int i = tid + k * 256;
        g_xh[(size_t)r * DIN + i] = siluf(row[DIN + i]);
    }
    if (tid < DST) {
        sB[tid] = siluf(row[2 * DIN + tid]);
    } else if (tid < 2 * DST) {
        sC[tid - DST] = siluf(row[2 * DIN + DST + (tid - DST)]);
    } else if (tid < 3 * DST) {
        int hh = tid - 2 * DST;
        float dv = row[2 * DIN + 2 * DST + hh] + dt_bias[hh];
        float dt = (dv > 20.f) ? dv : log1pf(expf(dv));
        g_dt[r * NH + hh] = dt;
        g_a[r * NH + hh] = -dt * expf(A_log[hh]);
    }
    __syncthreads();
    if (tid < 8) {
        int i = tid;
        float inv = powf(10000.f, -(float)i * 0.125f);
        float ang = (float)l * inv;
        float cs = cosf(ang), sn = sinf(ang);
        float b1 = sB[2 * i], b2 = sB[2 * i + 1];
        g_Bcq[r * DST + 2 * i]     = b1 * cs - b2 * sn;
        g_Bcq[r * DST + 2 * i + 1] = b1 * sn + b2 * cs;
    } else if (tid < 16) {
        int i = tid - 8;
        float inv = powf(10000.f, -(float)i * 0.125f);
        float ang = (float)l * inv;
        float cs = cosf(ang), sn = sinf(ang);
        float c1 = sC[2 * i], c2 = sC[2 * i + 1];
        g_Ccq[r * DST + 2 * i]     = c1 * cs - c2 * sn;
        g_Ccq[r * DST + 2 * i + 1] = c1 * sn + c2 * cs;
    } else if (tid < 32) {
        int j = tid;  // dims 16..31 pass through
        g_Bcq[r * DST + j] = sB[j];
        g_Ccq[r * DST + j] = sC[j];
    }
}

// ---------------- 4. scores = C·B^T per (b,chunk), shared by all heads ----------------
__global__ __launch_bounds__(256) void scores_kernel()
{
    int bid = blockIdx.x;           // b*64 + c
    int b = bid >> 6, c = bid & 63;
    __shared__ float sB[64][33];
    __shared__ float sC[64][32];
    int tid = threadIdx.x;
    int rbase = b * LEN + c * 64;
    for (int idx = tid; idx < 2048; idx += 256) {
        int l = idx >> 5, n = idx & 31;
        sB[l][n] = g_Bcq[(rbase + l) * DST + n];
        sC[l][n] = g_Ccq[(rbase + l) * DST + n];
    }
    __syncthreads();
    size_t obase = (size_t)bid * 4096;
    #pragma unroll 1
    for (int k = 0; k < 16; k++) {
        int idx = tid + k * 256;
        int l = idx >> 6, s_ = idx & 63;
        float acc = 0.f;
        #pragma unroll
        for (int n = 0; n < 32; n++) acc = fmaf(sC[l][n], sB[s_][n], acc);
        g_scores[obase + idx] = acc;
    }
}

// ---------------- 5. per-chunk local state: S[p,n] = sum_l Bk[l,n]*exp(Afin-Acs[l])*Xc[l,p] ----------------
__global__ __launch_bounds__(256) void chunkstate_kernel()
{
    int bid = blockIdx.x;           // ((b*64+c)*32+h)
    int h = bid & 31, c = (bid >> 5) & 63, b = bid >> 11;
    __shared__ float sAcs[64];
    __shared__ float sBk[64][32];
    __shared__ float sXd[64][64];
    int tid = threadIdx.x;
    int rbase = b * LEN + c * 64;
    if (tid == 0) {
        float s = 0.f;
        for (int l = 0; l < 64; l++) { s += g_a[(rbase + l) * NH + h]; sAcs[l] = s; }
    }
    for (int idx = tid; idx < 2048; idx += 256) {
        int l = idx >> 5, n = idx & 31;
        sBk[l][n] = g_Bcq[(rbase + l) * DST + n];
    }
    __syncthreads();
    float Afin = sAcs[63];
    for (int idx = tid; idx < 4096; idx += 256) {
        int l = idx >> 6, p = idx & 63;
        float d = g_dt[(rbase + l) * NH + h];
        sXd[l][p] = g_xh[(size_t)(rbase + l) * DIN + h * HD + p] * d * expf(Afin - sAcs[l]);
    }
    if (tid < 64) g_acs[(size_t)bid * 64 + tid] = sAcs[tid];
    __syncthreads();
    size_t sbase = (size_t)bid * 2048;
    #pragma unroll 1
    for (int k = 0; k < 8; k++) {
        int idx = tid + k * 256;
        int p = idx >> 5, n = idx & 31;
        float acc = 0.f;
        #pragma unroll
        for (int l = 0; l < 64; l++) acc = fmaf(sBk[l][n], sXd[l][p], acc);
        g_S[sbase + idx] = acc;
    }
}

// ---------------- 6. sequential scan over chunks: carry = exp(t_c)*carry + S_c ----------------
__global__ __launch_bounds__(256) void scan_kernel()
{
    int bid = blockIdx.x;           // q + 8*(h + 32*b)
    int q = bid & 7;
    int bh = bid >> 3;
    int h = bh & 31, b = bh >> 5;
    int tid = threadIdx.x;
    int v = q * 256 + tid;
    float carry = 0.f;
    for (int c = 0; c < NC; c++) {
        int cb = ((b * NC + c) * NH + h);
        float Tc = expf(g_acs[(size_t)cb * 64 + 63]);
        size_t base = (size_t)cb * 2048;
        g_Sin[base + v] = carry;
        carry = fmaf(Tc, carry, g_S[base + v]);
    }
}

// ---------------- 7. per-chunk output: y = (scores*L)@Xc + exp(Acs)·(Ck@Sin^T) + xh*D ----------------
__global__ __launch_bounds__(256) void output_kernel(const float* __restrict__ Dv)
{
    int bid = blockIdx.x;           // ((b*64+c)*32+h)
    int h = bid & 31, c = (bid >> 5) & 63, b = bid >> 11;
    __shared__ float sM[64][64];
    __shared__ float sX[64][64];
    __shared__ float sCk[64][32];
    __shared__ float sAcs[64];
    __shared__ float sEA[64];
    int tid = threadIdx.x;
    int rbase = b * LEN + c * 64;
    if (tid < 64) {
        float a = g_acs[(size_t)bid * 64 + tid];
        sAcs[tid] = a;
        sEA[tid]  = expf(a);
    }
    for (int idx = tid; idx < 2048; idx += 256) {
        int l = idx >> 5, n = idx & 31;
        sCk[l][n] = g_Ccq[(rbase + l) * DST + n];
    }
    __syncthreads();
    const float* sc = g_scores + (size_t)(b * NC + c) * 4096;
    #pragma unroll 1
    for (int k = 0; k < 16; k++) {
        int idx = tid + k * 256;
        int l = idx >> 6, s_ = idx & 63;
        float m = 0.f;
        if (s_ <= l) m = sc[idx] * expf(sAcs[l] - sAcs[s_]);
        sM[l][s_] = m;
        int p = s_;
        sX[l][p] = g_xh[(size_t)(rbase + l) * DIN + h * HD + p] * g_dt[(rbase + l) * NH + h];
    }
    // Sin for phase-B mapping (fixed p per thread)
    int p0 = tid & 63;
    float vreg[32];
    size_t sinbase = (size_t)bid * 2048 + (size_t)p0 * 32;
    #pragma unroll
    for (int n = 0; n < 32; n++) vreg[n] = g_Sin[sinbase + n];
    __syncthreads();

    // Phase A: Yd, 4x4 tile per thread
    int l0 = ((tid >> 4) & 15) << 2;
    int q0 = (tid & 15) << 2;
    float yd[4][4];
    #pragma unroll
    for (int i = 0; i < 4; i++)
        #pragma unroll
        for (int j = 0; j < 4; j++) yd[i][j] = 0.f;
    #pragma unroll 4
    for (int s = 0; s < 64; s++) {
        float4 xv = *reinterpret_cast<const float4*>(&sX[s][q0]);
        float xr[4] = {xv.x, xv.y, xv.z, xv.w};
        #pragma unroll
        for (int i = 0; i < 4; i++) {
            float mv = sM[l0 + i][s];
            #pragma unroll
            for (int j = 0; j < 4; j++) yd[i][j] = fmaf(mv, xr[j], yd[i][j]);
        }
    }
    __syncthreads();                 // everyone done reading sM
    #pragma unroll
    for (int i = 0; i < 4; i++)
        #pragma unroll
        for (int j = 0; j < 4; j++) sM[l0 + i][q0 + j] = yd[i][j];   // stage Yd in sM
    __syncthreads();

    // Phase B: combine Yd + exp(Acs[l])*Yo + xh*D  (fixed p = tid&63, 16 l's)
    float Dh = Dv[h];
    #pragma unroll 1
    for (int k = 0; k < 16; k++) {
        int idx = tid + k * 256;
        int l = idx >> 6, p = idx & 63;
        float yo = 0.f;
        #pragma unroll
        for (int n = 0; n < 32; n++) yo = fmaf(sCk[l][n], vreg[n], yo);
        float xhv = g_xh[(size_t)(rbase + l) * DIN + h * HD + p];
        g_y[(size_t)(rbase + l) * DIN + h * HD + p] = sM[l][p] + sEA[l] * yo + xhv * Dh;
    }
}

// ---------------- 8. gate with silu(z) + RMSNorm ----------------
__global__ __launch_bounds__(256) void gate_kernel(const float* __restrict__ rms_w)
{
    __shared__ float sb[32];
    int r = blockIdx.x, tid = threadIdx.x;
    const float* zr = g_zx + (size_t)r * NPROJ;
    const float* yr = g_y + (size_t)r * DIN;
    float v[8]; float ss = 0.f;
    #pragma unroll
    for (int k = 0; k < 8; k++) {
        int i = tid + k * 256;
        float z = zr[i];
        float val = yr[i] * siluf(z);
        v[k] = val; ss += val * val;
    }
    ss = blk_reduce(ss, sb);
    float scale = rsqrtf(ss * (1.f / DIN) + 1e-6f);
    float* outr = g_yn + (size_t)r * DIN;
    #pragma unroll
    for (int k = 0; k < 8; k++) {
        int i = tid + k * 256;
        outr[i] = v[k] * scale * rms_w[i];
    }
}

// ---------------- launch ----------------
extern "C" void kernel_launch(void* const* d_in, const int* in_sizes, int n_in,
                              void* d_out, int out_size)
{
    const float* x       = (const float*)d_in[0];
    const float* ln_w    = (const float*)d_in[1];
    const float* ln_b    = (const float*)d_in[2];
    const float* W_in    = (const float*)d_in[3];
    const float* dt_bias = (const float*)d_in[4];
    const float* A_log   = (const float*)d_in[5];
    const float* Dv      = (const float*)d_in[6];
    const float* rms_w   = (const float*)d_in[7];
    const float* W_out   = (const float*)d_in[8];
    float* out = (float*)d_out;

    float *pH = nullptr, *pZX = nullptr, *pYN = nullptr;
    cudaGetSymbolAddress((void**)&pH,  g_h);
    cudaGetSymbolAddress((void**)&pZX, g_zx);
    cudaGetSymbolAddress((void**)&pYN, g_yn);

    layernorm_kernel<<<NROWS, 256>>>(x, ln_w, ln_b);
    sgemm_kernel<<<dim3((NPROJ + 127) / 128, NROWS / 128), 256>>>(pH, W_in, nullptr, pZX,
                                                                  NROWS, NPROJ, DMODEL);
    prep_kernel<<<NROWS, 256>>>(dt_bias, A_log);
    scores_kernel<<<BSZ * NC, 256>>>();
    chunkstate_kernel<<<BSZ * NC * NH, 256>>>();
    scan_kernel<<<BSZ * NH * 8, 256>>>();
    output_kernel<<<BSZ * NC * NH, 256>>>(Dv);
    gate_kernel<<<NROWS, 256>>>(rms_w);
    sgemm_kernel<<<dim3(DMODEL / 128, NROWS / 128), 256>>>(pYN, W_out, x, out,
                                                           NROWS, DMODEL, DIN);
}

// round 5
// speedup vs baseline: 2.3258x; 2.3258x over previous
#include <cuda_runtime.h>
#include <math.h>
#include <stdint.h>

#define BSZ    4
#define LEN    4096
#define DMODEL 1024
#define DIN    2048
#define NH     32
#define HD     64
#define DST    32
#define NPROJ  4192
#define NC     64
#define NROWS  16384   // BSZ*LEN

// ---------------- scratch (device globals; no allocation allowed) ----------------
__device__ __align__(256) float g_h[NROWS * DMODEL];          // post-layernorm
__device__ __align__(256) float g_zx[NROWS * NPROJ];          // in_proj output
__device__ __align__(256) float g_xh[NROWS * DIN];            // silu(x-part)
__device__ __align__(256) float g_dt[NROWS * NH];             // softplus dt
__device__ __align__(256) float g_a[NROWS * NH];              // dt * A  (negative)
__device__ __align__(256) float g_Bcq[NROWS * DST];           // silu+rope B
__device__ __align__(256) float g_Ccq[NROWS * DST];           // silu+rope C
__device__ __align__(256) float g_scores[BSZ * NC * 64 * 64]; // C·B^T per (b,chunk)
__device__ __align__(256) float g_acs[BSZ * NC * NH * 64];    // per-chunk inclusive cumsum of a
__device__ __align__(256) float g_S[BSZ * NC * NH * HD * DST];   // local chunk states
__device__ __align__(256) float g_Sin[BSZ * NC * NH * HD * DST]; // carried-in states
__device__ __align__(256) float g_y[NROWS * DIN];             // SSD output
__device__ __align__(256) float g_yn[NROWS * DIN];            // gated+rmsnormed
__device__ __align__(256) float g_WinT[NPROJ * DMODEL];       // W_in^T  [N,K]
__device__ __align__(256) float g_WoutT[DMODEL * DIN];        // W_out^T [N,K]

__device__ __forceinline__ float siluf(float v) { return v / (1.f + expf(-v)); }

// ======================= PTX helpers =======================
__device__ __forceinline__ uint32_t smem_u32(const void* p) {
    uint32_t a;
    asm("{ .reg .u64 t; cvta.to.shared.u64 t, %1; cvt.u32.u64 %0, t; }" : "=r"(a) : "l"(p));
    return a;
}
__device__ __forceinline__ void cp_async16(uint32_t saddr, const void* gaddr) {
    asm volatile("cp.async.ca.shared.global [%0], [%1], 16;" :: "r"(saddr), "l"(gaddr));
}
#define CP_COMMIT() asm volatile("cp.async.commit_group;" ::: "memory")
#define CP_WAIT(N)  asm volatile("cp.async.wait_group %0;" :: "n"(N) : "memory")

__device__ __forceinline__ uint32_t f2tf32(float f) {
    uint32_t o;
    asm("cvt.rna.tf32.f32 %0, %1;" : "=r"(o) : "f"(f));
    return o;
}
__device__ __forceinline__ void mma_tf32(float* c, uint32_t a0, uint32_t a1, uint32_t a2, uint32_t a3,
                                         uint32_t b0, uint32_t b1) {
    asm volatile("mma.sync.aligned.m16n8k8.row.col.f32.tf32.tf32.f32 "
                 "{%0,%1,%2,%3}, {%4,%5,%6,%7}, {%8,%9}, {%0,%1,%2,%3};"
                 : "+f"(c[0]), "+f"(c[1]), "+f"(c[2]), "+f"(c[3])
                 : "r"(a0), "r"(a1), "r"(a2), "r"(a3), "r"(b0), "r"(b1));
}

// ---------------- transpose: src[R,C] -> dst[C,R] ----------------
__global__ __launch_bounds__(256) void transpose_kernel(
    const float* __restrict__ src, float* __restrict__ dst, int R, int C)
{
    __shared__ float t[32][33];
    int bx = blockIdx.x * 32, by = blockIdx.y * 32;
    int tx = threadIdx.x & 31, ty = threadIdx.x >> 5;   // 32 x 8
    #pragma unroll
    for (int k = 0; k < 4; k++) {
        int r = by + ty + k * 8;
        if (r < R && bx + tx < C) t[ty + k * 8][tx] = src[(size_t)r * C + bx + tx];
    }
    __syncthreads();
    #pragma unroll
    for (int k = 0; k < 4; k++) {
        int c = bx + ty + k * 8;
        if (c < C && by + tx < R) dst[(size_t)c * R + by + tx] = t[tx][ty + k * 8];
    }
}

// ---------------- tf32 mma.sync GEMM: Cout[M,N] = A[M,K] @ Bt[N,K]^T (+Cadd) ----------------
// CTA tile 128x128, K-tile 16, cp.async double buffer, 256 threads = 8 warps (2x4),
// warp tile 64x32 via m16n8k8.
#define SROW 20   // smem row stride in floats (conflict-free for fragment pattern)

__global__ __launch_bounds__(256) void mma_gemm_kernel(
    const float* __restrict__ A, const float* __restrict__ Bt,
    const float* __restrict__ Cadd, float* __restrict__ Cout,
    int M, int N, int K)
{
    __shared__ float sA[2][128 * SROW];
    __shared__ float sB[2][128 * SROW];
    const int tid = threadIdx.x;
    const int lane = tid & 31;
    const int wid = tid >> 5;
    const int wm = (wid >> 2) * 64;   // warp m offset (0 or 64)
    const int wn = (wid & 3) * 32;    // warp n offset (0,32,64,96)
    const int bm = blockIdx.y * 128;
    const int bn = blockIdx.x * 128;
    const int row = lane >> 2;        // 0..7
    const int col = lane & 3;         // 0..3

    const uint32_t sA0 = smem_u32(&sA[0][0]);
    const uint32_t sB0 = smem_u32(&sB[0][0]);

    float c[4][4][4];
    #pragma unroll
    for (int i = 0; i < 4; i++)
        #pragma unroll
        for (int j = 0; j < 4; j++)
            #pragma unroll
            for (int q = 0; q < 4; q++) c[i][j][q] = 0.f;

    const int nk = K >> 4;

    // ---- tile loader ----
    auto load_tile = [&](int buf, int kt) {
        const int k0 = kt << 4;
        #pragma unroll
        for (int i = 0; i < 2; i++) {
            int idx = tid + i * 256;         // 0..511
            int r = idx >> 2;                // 0..127
            int q = idx & 3;                 // 0..3 (float4 chunk in row)
            uint32_t soff = (uint32_t)((r * SROW + q * 4) * 4);
            cp_async16(sA0 + buf * (128 * SROW * 4) + soff,
                       A + (size_t)(bm + r) * K + k0 + q * 4);
            int gn = bn + r; if (gn >= N) gn = N - 1;
            cp_async16(sB0 + buf * (128 * SROW * 4) + soff,
                       Bt + (size_t)gn * K + k0 + q * 4);
        }
        CP_COMMIT();
    };

    load_tile(0, 0);

    int buf = 0;
    for (int kt = 0; kt < nk; kt++) {
        if (kt + 1 < nk) { load_tile(buf ^ 1, kt + 1); CP_WAIT(1); }
        else             { CP_WAIT(0); }
        __syncthreads();

        const float* pA = sA[buf];
        const float* pB = sB[buf];
        #pragma unroll
        for (int ks = 0; ks < 2; ks++) {
            const int kc = col + ks * 8;
            uint32_t bfr[4][2];
            #pragma unroll
            for (int nf = 0; nf < 4; nf++) {
                int n = wn + nf * 8 + row;
                bfr[nf][0] = f2tf32(pB[n * SROW + kc]);
                bfr[nf][1] = f2tf32(pB[n * SROW + kc + 4]);
            }
            #pragma unroll
            for (int mf = 0; mf < 4; mf++) {
                int m = wm + mf * 16 + row;
                uint32_t a0 = f2tf32(pA[m * SROW + kc]);
                uint32_t a1 = f2tf32(pA[(m + 8) * SROW + kc]);
                uint32_t a2 = f2tf32(pA[m * SROW + kc + 4]);
                uint32_t a3 = f2tf32(pA[(m + 8) * SROW + kc + 4]);
                #pragma unroll
                for (int nf = 0; nf < 4; nf++)
                    mma_tf32(c[mf][nf], a0, a1, a2, a3, bfr[nf][0], bfr[nf][1]);
            }
        }
        __syncthreads();
        buf ^= 1;
    }

    // ---- epilogue ----
    #pragma unroll
    for (int mf = 0; mf < 4; mf++) {
        int m0 = bm + wm + mf * 16 + row;
        #pragma unroll
        for (int nf = 0; nf < 4; nf++) {
            int c0 = bn + wn + nf * 8 + col * 2;
            if (c0 < N) {
                float2 v0 = make_float2(c[mf][nf][0], c[mf][nf][1]);
                float2 v1 = make_float2(c[mf][nf][2], c[mf][nf][3]);
                if (Cadd) {
                    float2 u0 = *reinterpret_cast<const float2*>(Cadd + (size_t)m0 * N + c0);
                    float2 u1 = *reinterpret_cast<const float2*>(Cadd + (size_t)(m0 + 8) * N + c0);
                    v0.x += u0.x; v0.y += u0.y; v1.x += u1.x; v1.y += u1.y;
                }
                *reinterpret_cast<float2*>(Cout + (size_t)m0 * N + c0) = v0;
                *reinterpret_cast<float2*>(Cout + (size_t)(m0 + 8) * N + c0) = v1;
            }
        }
    }
}

// ---------------- block reduce helper ----------------
__device__ __forceinline__ float blk_reduce(float v, float* sb) {
    #pragma unroll
    for (int o = 16; o > 0; o >>= 1) v += __shfl_down_sync(0xffffffffu, v, o);
    int lane = threadIdx.x & 31, w = threadIdx.x >> 5;
    if (lane == 0) sb[w] = v;
    __syncthreads();
    if (threadIdx.x < 32) {
        v = (threadIdx.x < (blockDim.x >> 5)) ? sb[threadIdx.x] : 0.f;
        #pragma unroll
        for (int o = 4; o > 0; o >>= 1) v += __shfl_down_sync(0xffffffffu, v, o);
        if (threadIdx.x == 0) sb[0] = v;
    }
    __syncthreads();
    float r = sb[0];
    __syncthreads();
    return r;
}

// ---------------- 1. LayerNorm ----------------
__global__ __launch_bounds__(256) void layernorm_kernel(
    const float* __restrict__ x, const float* __restrict__ w, const float* __restrict__ b)
{
    __shared__ float sb[32];
    int r = blockIdx.x, tid = threadIdx.x;
    const float* xr = x + (size_t)r * DMODEL;
    float v[4], s = 0.f, sq = 0.f;
    #pragma unroll
    for (int k = 0; k < 4; k++) { int i = tid + k * 256; v[k] = xr[i]; s += v[k]; sq += v[k] * v[k]; }
    s  = blk_reduce(s, sb);
    sq = blk_reduce(sq, sb);
    float mean = s * (1.f / DMODEL);
    float var  = sq * (1.f / DMODEL) - mean * mean;
    float inv  = rsqrtf(var + 1e-6f);
    float* hr = g_h + (size_t)r * DMODEL;
    #pragma unroll
    for (int k = 0; k < 4; k++) { int i = tid + k * 256; hr[i] = (v[k] - mean) * inv * w[i] + b[i]; }
}

// ---------------- 3. split + silu + softplus + rope ----------------
__global__ __launch_bounds__(256) void prep_kernel(
    const float* __restrict__ dt_bias, const float* __restrict__ A_log)
{
    int r = blockIdx.x, tid = threadIdx.x;
    int l = r & (LEN - 1);
    const float* row = g_zx + (size_t)r * NPROJ;
    __shared__ float sB[DST], sC[DST];
    #pragma unroll
    for (int k = 0; k < 8; k++) {
        int i = tid + k * 256;
        g_xh[(size_t)r * DIN + i] = siluf(row[DIN + i]);
    }
    if (tid < DST) {
        sB[tid] = siluf(row[2 * DIN + tid]);
    } else if (tid < 2 * DST) {
        sC[tid - DST] = siluf(row[2 * DIN + DST + (tid - DST)]);
    } else if (tid < 3 * DST) {
        int hh = tid - 2 * DST;
        float dv = row[2 * DIN + 2 * DST + hh] + dt_bias[hh];
        float dt = (dv > 20.f) ? dv : log1pf(expf(dv));
        g_dt[r * NH + hh] = dt;
        g_a[r * NH + hh] = -dt * expf(A_log[hh]);
    }
    __syncthreads();
    if (tid < 8) {
        int i = tid;
        float inv = powf(10000.f, -(float)i * 0.125f);
        float ang = (float)l * inv;
        float cs = cosf(ang), sn = sinf(ang);
        float b1 = sB[2 * i], b2 = sB[2 * i + 1];
        g_Bcq[r * DST + 2 * i]     = b1 * cs - b2 * sn;
        g_Bcq[r * DST + 2 * i + 1] = b1 * sn + b2 * cs;
    } else if (tid < 16) {
        int i = tid - 8;
        float inv = powf(10000.f, -(float)i * 0.125f);
        float ang = (float)l * inv;
        float cs = cosf(ang), sn = sinf(ang);
        float c1 = sC[2 * i], c2 = sC[2 * i + 1];
        g_Ccq[r * DST + 2 * i]     = c1 * cs - c2 * sn;
        g_Ccq[r * DST + 2 * i + 1] = c1 * sn + c2 * cs;
    } else if (tid < 32) {
        int j = tid;  // dims 16..31 pass through
        g_Bcq[r * DST + j] = sB[j];
        g_Ccq[r * DST + j] = sC[j];
    }
}

// ---------------- 4. scores = C·B^T per (b,chunk), shared by all heads ----------------
__global__ __launch_bounds__(256) void scores_kernel()
{
    int bid = blockIdx.x;           // b*64 + c
    int b = bid >> 6, c = bid & 63;
    __shared__ float sB[64][33];
    __shared__ float sC[64][32];
    int tid = threadIdx.x;
    int rbase = b * LEN + c * 64;
    for (int idx = tid; idx < 2048; idx += 256) {
        int l = idx >> 5, n = idx & 31;
        sB[l][n] = g_Bcq[(rbase + l) * DST + n];
        sC[l][n] = g_Ccq[(rbase + l) * DST + n];
    }
    __syncthreads();
    size_t obase = (size_t)bid * 4096;
    #pragma unroll 1
    for (int k = 0; k < 16; k++) {
        int idx = tid + k * 256;
        int l = idx >> 6, s_ = idx & 63;
        float acc = 0.f;
        #pragma unroll
        for (int n = 0; n < 32; n++) acc = fmaf(sC[l][n], sB[s_][n], acc);
        g_scores[obase + idx] = acc;
    }
}

// ---------------- 5. per-chunk local state ----------------
__global__ __launch_bounds__(256) void chunkstate_kernel()
{
    int bid = blockIdx.x;           // ((b*64+c)*32+h)
    int h = bid & 31, c = (bid >> 5) & 63, b = bid >> 11;
    __shared__ float sAcs[64];
    __shared__ float sBk[64][32];
    __shared__ float sXd[64][64];
    int tid = threadIdx.x;
    int rbase = b * LEN + c * 64;
    if (tid == 0) {
        float s = 0.f;
        for (int l = 0; l < 64; l++) { s += g_a[(rbase + l) * NH + h]; sAcs[l] = s; }
    }
    for (int idx = tid; idx < 2048; idx += 256) {
        int l = idx >> 5, n = idx & 31;
        sBk[l][n] = g_Bcq[(rbase + l) * DST + n];
    }
    __syncthreads();
    float Afin = sAcs[63];
    for (int idx = tid; idx < 4096; idx += 256) {
        int l = idx >> 6, p = idx & 63;
        float d = g_dt[(rbase + l) * NH + h];
        sXd[l][p] = g_xh[(size_t)(rbase + l) * DIN + h * HD + p] * d * expf(Afin - sAcs[l]);
    }
    if (tid < 64) g_acs[(size_t)bid * 64 + tid] = sAcs[tid];
    __syncthreads();
    size_t sbase = (size_t)bid * 2048;
    #pragma unroll 1
    for (int k = 0; k < 8; k++) {
        int idx = tid + k * 256;
        int p = idx >> 5, n = idx & 31;
        float acc = 0.f;
        #pragma unroll
        for (int l = 0; l < 64; l++) acc = fmaf(sBk[l][n], sXd[l][p], acc);
        g_S[sbase + idx] = acc;
    }
}

// ---------------- 6. sequential scan over chunks ----------------
__global__ __launch_bounds__(256) void scan_kernel()
{
    int bid = blockIdx.x;           // q + 8*(h + 32*b)
    int q = bid & 7;
    int bh = bid >> 3;
    int h = bh & 31, b = bh >> 5;
    int tid = threadIdx.x;
    int v = q * 256 + tid;
    float carry = 0.f;
    for (int c = 0; c < NC; c++) {
        int cb = ((b * NC + c) * NH + h);
        float Tc = expf(g_acs[(size_t)cb * 64 + 63]);
        size_t base = (size_t)cb * 2048;
        g_Sin[base + v] = carry;
        carry = fmaf(Tc, carry, g_S[base + v]);
    }
}

// ---------------- 7. per-chunk output ----------------
__global__ __launch_bounds__(256) void output_kernel(const float* __restrict__ Dv)
{
    int bid = blockIdx.x;           // ((b*64+c)*32+h)
    int h = bid & 31, c = (bid >> 5) & 63, b = bid >> 11;
    __shared__ float sM[64][64];
    __shared__ float sX[64][64];
    __shared__ float sCk[64][32];
    __shared__ float sAcs[64];
    __shared__ float sEA[64];
    int tid = threadIdx.x;
    int rbase = b * LEN + c * 64;
    if (tid < 64) {
        float a = g_acs[(size_t)bid * 64 + tid];
        sAcs[tid] = a;
        sEA[tid]  = expf(a);
    }
    for (int idx = tid; idx < 2048; idx += 256) {
        int l = idx >> 5, n = idx & 31;
        sCk[l][n] = g_Ccq[(rbase + l) * DST + n];
    }
    __syncthreads();
    const float* sc = g_scores + (size_t)(b * NC + c) * 4096;
    #pragma unroll 1
    for (int k = 0; k < 16; k++) {
        int idx = tid + k * 256;
        int l = idx >> 6, s_ = idx & 63;
        float m = 0.f;
        if (s_ <= l) m = sc[idx] * expf(sAcs[l] - sAcs[s_]);
        sM[l][s_] = m;
        int p = s_;
        sX[l][p] = g_xh[(size_t)(rbase + l) * DIN + h * HD + p] * g_dt[(rbase + l) * NH + h];
    }
    int p0 = tid & 63;
    float vreg[32];
    size_t sinbase = (size_t)bid * 2048 + (size_t)p0 * 32;
    #pragma unroll
    for (int n = 0; n < 32; n++) vreg[n] = g_Sin[sinbase + n];
    __syncthreads();

    int l0 = ((tid >> 4) & 15) << 2;
    int q0 = (tid & 15) << 2;
    float yd[4][4];
    #pragma unroll
    for (int i = 0; i < 4; i++)
        #pragma unroll
        for (int j = 0; j < 4; j++) yd[i][j] = 0.f;
    #pragma unroll 4
    for (int s = 0; s < 64; s++) {
        float4 xv = *reinterpret_cast<const float4*>(&sX[s][q0]);
        float xr[4] = {xv.x, xv.y, xv.z, xv.w};
        #pragma unroll
        for (int i = 0; i < 4; i++) {
            float mv = sM[l0 + i][s];
            #pragma unroll
            for (int j = 0; j < 4; j++) yd[i][j] = fmaf(mv, xr[j], yd[i][j]);
        }
    }
    __syncthreads();
    #pragma unroll
    for (int i = 0; i < 4; i++)
        #pragma unroll
        for (int j = 0; j < 4; j++) sM[l0 + i][q0 + j] = yd[i][j];
    __syncthreads();

    float Dh = Dv[h];
    #pragma unroll 1
    for (int k = 0; k < 16; k++) {
        int idx = tid + k * 256;
        int l = idx >> 6, p = idx & 63;
        float yo = 0.f;
        #pragma unroll
        for (int n = 0; n < 32; n++) yo = fmaf(sCk[l][n], vreg[n], yo);
        float xhv = g_xh[(size_t)(rbase + l) * DIN + h * HD + p];
        g_y[(size_t)(rbase + l) * DIN + h * HD + p] = sM[l][p] + sEA[l] * yo + xhv * Dh;
    }
}

// ---------------- 8. gate with silu(z) + RMSNorm ----------------
__global__ __launch_bounds__(256) void gate_kernel(const float* __restrict__ rms_w)
{
    __shared__ float sb[32];
    int r = blockIdx.x, tid = threadIdx.x;
    const float* zr = g_zx + (size_t)r * NPROJ;
    const float* yr = g_y + (size_t)r * DIN;
    float v[8]; float ss = 0.f;
    #pragma unroll
    for (int k = 0; k < 8; k++) {
        int i = tid + k * 256;
        float z = zr[i];
        float val = yr[i] * siluf(z);
        v[k] = val; ss += val * val;
    }
    ss = blk_reduce(ss, sb);
    float scale = rsqrtf(ss * (1.f / DIN) + 1e-6f);
    float* outr = g_yn + (size_t)r * DIN;
    #pragma unroll
    for (int k = 0; k < 8; k++) {
        int i = tid + k * 256;
        outr[i] = v[k] * scale * rms_w[i];
    }
}

// ---------------- launch ----------------
extern "C" void kernel_launch(void* const* d_in, const int* in_sizes, int n_in,
                              void* d_out, int out_size)
{
    const float* x       = (const float*)d_in[0];
    const float* ln_w    = (const float*)d_in[1];
    const float* ln_b    = (const float*)d_in[2];
    const float* W_in    = (const float*)d_in[3];
    const float* dt_bias = (const float*)d_in[4];
    const float* A_log   = (const float*)d_in[5];
    const float* Dv      = (const float*)d_in[6];
    const float* rms_w   = (const float*)d_in[7];
    const float* W_out   = (const float*)d_in[8];
    float* out = (float*)d_out;

    float *pH = nullptr, *pZX = nullptr, *pYN = nullptr, *pWinT = nullptr, *pWoutT = nullptr;
    cudaGetSymbolAddress((void**)&pH,  g_h);
    cudaGetSymbolAddress((void**)&pZX, g_zx);
    cudaGetSymbolAddress((void**)&pYN, g_yn);
    cudaGetSymbolAddress((void**)&pWinT, g_WinT);
    cudaGetSymbolAddress((void**)&pWoutT, g_WoutT);

    transpose_kernel<<<dim3(NPROJ / 32, DMODEL / 32), 256>>>(W_in, pWinT, DMODEL, NPROJ);
    transpose_kernel<<<dim3(DMODEL / 32, DIN / 32), 256>>>(W_out, pWoutT, DIN, DMODEL);

    layernorm_kernel<<<NROWS, 256>>>(x, ln_w, ln_b);
    mma_gemm_kernel<<<dim3((NPROJ + 127) / 128, NROWS / 128), 256>>>(
        pH, pWinT, nullptr, pZX, NROWS, NPROJ, DMODEL);
    prep_kernel<<<NROWS, 256>>>(dt_bias, A_log);
    scores_kernel<<<BSZ * NC, 256>>>();
    chunkstate_kernel<<<BSZ * NC * NH, 256>>>();
    scan_kernel<<<BSZ * NH * 8, 256>>>();
    output_kernel<<<BSZ * NC * NH, 256>>>(Dv);
    gate_kernel<<<NROWS, 256>>>(rms_w);
    mma_gemm_kernel<<<dim3(DMODEL / 128, NROWS / 128), 256>>>(
        pYN, pWoutT, x, out, NROWS, DMODEL, DIN);
}

// round 6
// speedup vs baseline: 2.3312x; 1.0023x over previous
#include <cuda_runtime.h>
#include <math.h>
#include <stdint.h>

#define BSZ    4
#define LEN    4096
#define DMODEL 1024
#define DIN    2048
#define NH     32
#define HD     64
#define DST    32
#define NPROJ  4192
#define NC     64
#define NROWS  16384   // BSZ*LEN

// ---------------- scratch (device globals; no allocation allowed) ----------------
__device__ __align__(256) float g_h[NROWS * DMODEL];          // post-layernorm
__device__ __align__(256) float g_zx[NROWS * NPROJ];          // in_proj output
__device__ __align__(256) float g_xh[NROWS * DIN];            // silu(x-part)
__device__ __align__(256) float g_dt[NROWS * NH];             // softplus dt
__device__ __align__(256) float g_a[NROWS * NH];              // dt * A  (negative)
__device__ __align__(256) float g_Bcq[NROWS * DST];           // silu+rope B
__device__ __align__(256) float g_Ccq[NROWS * DST];           // silu+rope C
__device__ __align__(256) float g_scores[BSZ * NC * 64 * 64]; // C·B^T per (b,chunk)
__device__ __align__(256) float g_acs[BSZ * NC * NH * 64];    // per-chunk inclusive cumsum of a
__device__ __align__(256) float g_S[BSZ * NC * NH * HD * DST];   // local chunk states
__device__ __align__(256) float g_Sin[BSZ * NC * NH * HD * DST]; // carried-in states
__device__ __align__(256) float g_y[NROWS * DIN];             // SSD output
__device__ __align__(256) float g_yn[NROWS * DIN];            // gated+rmsnormed
__device__ __align__(256) float g_WinT[NPROJ * DMODEL];       // W_in^T  [N,K]
__device__ __align__(256) float g_WoutT[DMODEL * DIN];        // W_out^T [N,K]

__device__ __forceinline__ float siluf(float v) { return v / (1.f + expf(-v)); }

// ======================= PTX helpers =======================
__device__ __forceinline__ uint32_t smem_u32(const void* p) {
    uint32_t a;
    asm("{ .reg .u64 t; cvta.to.shared.u64 t, %1; cvt.u32.u64 %0, t; }" : "=r"(a) : "l"(p));
    return a;
}
__device__ __forceinline__ void cp_async16(uint32_t saddr, const void* gaddr) {
    asm volatile("cp.async.ca.shared.global [%0], [%1], 16;" :: "r"(saddr), "l"(gaddr));
}
#define CP_COMMIT() asm volatile("cp.async.commit_group;" ::: "memory")
#define CP_WAIT(N)  asm volatile("cp.async.wait_group %0;" :: "n"(N) : "memory")

__device__ __forceinline__ uint32_t f2tf32(float f) {
    uint32_t o;
    asm("cvt.rna.tf32.f32 %0, %1;" : "=r"(o) : "f"(f));
    return o;
}
__device__ __forceinline__ void mma_tf32(float* c, uint32_t a0, uint32_t a1, uint32_t a2, uint32_t a3,
                                         uint32_t b0, uint32_t b1) {
    asm volatile("mma.sync.aligned.m16n8k8.row.col.f32.tf32.tf32.f32 "
                 "{%0,%1,%2,%3}, {%4,%5,%6,%7}, {%8,%9}, {%0,%1,%2,%3};"
                 : "+f"(c[0]), "+f"(c[1]), "+f"(c[2]), "+f"(c[3])
                 : "r"(a0), "r"(a1), "r"(a2), "r"(a3), "r"(b0), "r"(b1));
}

// ---------------- transpose: src[R,C] -> dst[C,R] ----------------
__global__ __launch_bounds__(256) void transpose_kernel(
    const float* __restrict__ src, float* __restrict__ dst, int R, int C)
{
    __shared__ float t[32][33];
    int bx = blockIdx.x * 32, by = blockIdx.y * 32;
    int tx = threadIdx.x & 31, ty = threadIdx.x >> 5;   // 32 x 8
    #pragma unroll
    for (int k = 0; k < 4; k++) {
        int r = by + ty + k * 8;
        if (r < R && bx + tx < C) t[ty + k * 8][tx] = src[(size_t)r * C + bx + tx];
    }
    __syncthreads();
    #pragma unroll
    for (int k = 0; k < 4; k++) {
        int c = bx + ty + k * 8;
        if (c < C && by + tx < R) dst[(size_t)c * R + by + tx] = t[tx][ty + k * 8];
    }
}

// ---------------- tf32 mma.sync GEMM: Cout[M,N] = A[M,K] @ Bt[N,K]^T (+Cadd) ----------------
// CTA tile 128x128, K-tile 16, cp.async double buffer, 256 threads = 8 warps (2x4),
// warp tile 64x32 via m16n8k8.
#define SROW 20   // smem row stride in floats (conflict-free for fragment pattern)

__global__ __launch_bounds__(256) void mma_gemm_kernel(
    const float* __restrict__ A, const float* __restrict__ Bt,
    const float* __restrict__ Cadd, float* __restrict__ Cout,
    int M, int N, int K)
{
    __shared__ float sA[2][128 * SROW];
    __shared__ float sB[2][128 * SROW];
    const int tid = threadIdx.x;
    const int lane = tid & 31;
    const int wid = tid >> 5;
    const int wm = (wid >> 2) * 64;   // warp m offset (0 or 64)
    const int wn = (wid & 3) * 32;    // warp n offset (0,32,64,96)
    const int bm = blockIdx.y * 128;
    const int bn = blockIdx.x * 128;
    const int row = lane >> 2;        // 0..7
    const int col = lane & 3;         // 0..3

    const uint32_t sA0 = smem_u32(&sA[0][0]);
    const uint32_t sB0 = smem_u32(&sB[0][0]);

    float c[4][4][4];
    #pragma unroll
    for (int i = 0; i < 4; i++)
        #pragma unroll
        for (int j = 0; j < 4; j++)
            #pragma unroll
            for (int q = 0; q < 4; q++) c[i][j][q] = 0.f;

    const int nk = K >> 4;

    // ---- tile loader ----
    auto load_tile = [&](int buf, int kt) {
        const int k0 = kt << 4;
        #pragma unroll
        for (int i = 0; i < 2; i++) {
            int idx = tid + i * 256;         // 0..511
            int r = idx >> 2;                // 0..127
            int q = idx & 3;                 // 0..3 (float4 chunk in row)
            uint32_t soff = (uint32_t)((r * SROW + q * 4) * 4);
            cp_async16(sA0 + buf * (128 * SROW * 4) + soff,
                       A + (size_t)(bm + r) * K + k0 + q * 4);
            int gn = bn + r; if (gn >= N) gn = N - 1;
            cp_async16(sB0 + buf * (128 * SROW * 4) + soff,
                       Bt + (size_t)gn * K + k0 + q * 4);
        }
        CP_COMMIT();
    };

    load_tile(0, 0);

    int buf = 0;
    for (int kt = 0; kt < nk; kt++) {
        if (kt + 1 < nk) { load_tile(buf ^ 1, kt + 1); CP_WAIT(1); }
        else             { CP_WAIT(0); }
        __syncthreads();

        const float* pA = sA[buf];
        const float* pB = sB[buf];
        #pragma unroll
        for (int ks = 0; ks < 2; ks++) {
            const int kc = col + ks * 8;
            uint32_t bfr[4][2];
            #pragma unroll
            for (int nf = 0; nf < 4; nf++) {
                int n = wn + nf * 8 + row;
                bfr[nf][0] = f2tf32(pB[n * SROW + kc]);
                bfr[nf][1] = f2tf32(pB[n * SROW + kc + 4]);
            }
            #pragma unroll
            for (int mf = 0; mf < 4; mf++) {
                int m = wm + mf * 16 + row;
                uint32_t a0 = f2tf32(pA[m * SROW + kc]);
                uint32_t a1 = f2tf32(pA[(m + 8) * SROW + kc]);
                uint32_t a2 = f2tf32(pA[m * SROW + kc + 4]);
                uint32_t a3 = f2tf32(pA[(m + 8) * SROW + kc + 4]);
                #pragma unroll
                for (int nf = 0; nf < 4; nf++)
                    mma_tf32(c[mf][nf], a0, a1, a2, a3, bfr[nf][0], bfr[nf][1]);
            }
        }
        __syncthreads();
        buf ^= 1;
    }

    // ---- epilogue ----
    #pragma unroll
    for (int mf = 0; mf < 4; mf++) {
        int m0 = bm + wm + mf * 16 + row;
        #pragma unroll
        for (int nf = 0; nf < 4; nf++) {
            int c0 = bn + wn + nf * 8 + col * 2;
            if (c0 < N) {
                float2 v0 = make_float2(c[mf][nf][0], c[mf][nf][1]);
                float2 v1 = make_float2(c[mf][nf][2], c[mf][nf][3]);
                if (Cadd) {
                    float2 u0 = *reinterpret_cast<const float2*>(Cadd + (size_t)m0 * N + c0);
                    float2 u1 = *reinterpret_cast<const float2*>(Cadd + (size_t)(m0 + 8) * N + c0);
                    v0.x += u0.x; v0.y += u0.y; v1.x += u1.x; v1.y += u1.y;
                }
                *reinterpret_cast<float2*>(Cout + (size_t)m0 * N + c0) = v0;
                *reinterpret_cast<float2*>(Cout + (size_t)(m0 + 8) * N + c0) = v1;
            }
        }
    }
}

// ---------------- block reduce helper ----------------
__device__ __forceinline__ float blk_reduce(float v, float* sb) {
    #pragma unroll
    for (int o = 16; o > 0; o >>= 1) v += __shfl_down_sync(0xffffffffu, v, o);
    int lane = threadIdx.x & 31, w = threadIdx.x >> 5;
    if (lane == 0) sb[w] = v;
    __syncthreads();
    if (threadIdx.x < 32) {
        v = (threadIdx.x < (blockDim.x >> 5)) ? sb[threadIdx.x] : 0.f;
        #pragma unroll
        for (int o = 4; o > 0; o >>= 1) v += __shfl_down_sync(0xffffffffu, v, o);
        if (threadIdx.x == 0) sb[0] = v;
    }
    __syncthreads();
    float r = sb[0];
    __syncthreads();
    return r;
}

// ---------------- 1. LayerNorm ----------------
__global__ __launch_bounds__(256) void layernorm_kernel(
    const float* __restrict__ x, const float* __restrict__ w, const float* __restrict__ b)
{
    __shared__ float sb[32];
    int r = blockIdx.x, tid = threadIdx.x;
    const float* xr = x + (size_t)r * DMODEL;
    float v[4], s = 0.f, sq = 0.f;
    #pragma unroll
    for (int k = 0; k < 4; k++) { int i = tid + k * 256; v[k] = xr[i]; s += v[k]; sq += v[k] * v[k]; }
    s  = blk_reduce(s, sb);
    sq = blk_reduce(sq, sb);
    float mean = s * (1.f / DMODEL);
    float var  = sq * (1.f / DMODEL) - mean * mean;
    float inv  = rsqrtf(var + 1e-6f);
    float* hr = g_h + (size_t)r * DMODEL;
    #pragma unroll
    for (int k = 0; k < 4; k++) { int i = tid + k * 256; hr[i] = (v[k] - mean) * inv * w[i] + b[i]; }
}

// ---------------- 3. split + silu + softplus + rope ----------------
__global__ __launch_bounds__(256) void prep_kernel(
    const float* __restrict__ dt_bias, const float* __restrict__ A_log)
{
    int r = blockIdx.x, tid = threadIdx.x;
    int l = r & (LEN - 1);
    const float* row = g_zx + (size_t)r * NPROJ;
    __shared__ float sB[DST], sC[DST];
    #pragma unroll
    for (int k = 0; k < 8; k++) {
        int i = tid + k * 256;
        g_xh[(size_t)r * DIN + i] = siluf(row[DIN + i]);
    }
    if (tid < DST) {
        sB[tid] = siluf(row[2 * DIN + tid]);
    } else if (tid < 2 * DST) {
        sC[tid - DST] = siluf(row[2 * DIN + DST + (tid - DST)]);
    } else if (tid < 3 * DST) {
        int hh = tid - 2 * DST;
        float dv = row[2 * DIN + 2 * DST + hh] + dt_bias[hh];
        float dt = (dv > 20.f) ? dv : log1pf(expf(dv));
        g_dt[r * NH + hh] = dt;
        g_a[r * NH + hh] = -dt * expf(A_log[hh]);
    }
    __syncthreads();
    if (tid < 8) {
        int i = tid;
        float inv = powf(10000.f, -(float)i * 0.125f);
        float ang = (float)l * inv;
        float cs = cosf(ang), sn = sinf(ang);
        float b1 = sB[2 * i], b2 = sB[2 * i + 1];
        g_Bcq[r * DST + 2 * i]     = b1 * cs - b2 * sn;
        g_Bcq[r * DST + 2 * i + 1] = b1 * sn + b2 * cs;
    } else if (tid < 16) {
        int i = tid - 8;
        float inv = powf(10000.f, -(float)i * 0.125f);
        float ang = (float)l * inv;
        float cs = cosf(ang), sn = sinf(ang);
        float c1 = sC[2 * i], c2 = sC[2 * i + 1];
        g_Ccq[r * DST + 2 * i]     = c1 * cs - c2 * sn;
        g_Ccq[r * DST + 2 * i + 1] = c1 * sn + c2 * cs;
    } else if (tid < 32) {
        int j = tid;  // dims 16..31 pass through
        g_Bcq[r * DST + j] = sB[j];
        g_Ccq[r * DST + j] = sC[j];
    }
}

// ---------------- 4. scores = C·B^T per (b,chunk), shared by all heads ----------------
__global__ __launch_bounds__(256) void scores_kernel()
{
    int bid = blockIdx.x;           // b*64 + c
    int b = bid >> 6, c = bid & 63;
    __shared__ float sB[64][33];
    __shared__ float sC[64][32];
    int tid = threadIdx.x;
    int rbase = b * LEN + c * 64;
    for (int idx = tid; idx < 2048; idx += 256) {
        int l = idx >> 5, n = idx & 31;
        sB[l][n] = g_Bcq[(rbase + l) * DST + n];
        sC[l][n] = g_Ccq[(rbase + l) * DST + n];
    }
    __syncthreads();
    size_t obase = (size_t)bid * 4096;
    #pragma unroll 1
    for (int k = 0; k < 16; k++) {
        int idx = tid + k * 256;
        int l = idx >> 6, s_ = idx & 63;
        float acc = 0.f;
        #pragma unroll
        for (int n = 0; n < 32; n++) acc = fmaf(sC[l][n], sB[s_][n], acc);
        g_scores[obase + idx] = acc;
    }
}

// ---------------- 5. per-chunk local state ----------------
__global__ __launch_bounds__(256) void chunkstate_kernel()
{
    int bid = blockIdx.x;           // ((b*64+c)*32+h)
    int h = bid & 31, c = (bid >> 5) & 63, b = bid >> 11;
    __shared__ float sAcs[64];
    __shared__ float sBk[64][32];
    __shared__ float sXd[64][64];
    int tid = threadIdx.x;
    int rbase = b * LEN + c * 64;
    if (tid == 0) {
        float s = 0.f;
        for (int l = 0; l < 64; l++) { s += g_a[(rbase + l) * NH + h]; sAcs[l] = s; }
    }
    for (int idx = tid; idx < 2048; idx += 256) {
        int l = idx >> 5, n = idx & 31;
        sBk[l][n] = g_Bcq[(rbase + l) * DST + n];
    }
    __syncthreads();
    float Afin = sAcs[63];
    for (int idx = tid; idx < 4096; idx += 256) {
        int l = idx >> 6, p = idx & 63;
        float d = g_dt[(rbase + l) * NH + h];
        sXd[l][p] = g_xh[(size_t)(rbase + l) * DIN + h * HD + p] * d * expf(Afin - sAcs[l]);
    }
    if (tid < 64) g_acs[(size_t)bid * 64 + tid] = sAcs[tid];
    __syncthreads();
    size_t sbase = (size_t)bid * 2048;
    #pragma unroll 1
    for (int k = 0; k < 8; k++) {
        int idx = tid + k * 256;
        int p = idx >> 5, n = idx & 31;
        float acc = 0.f;
        #pragma unroll
        for (int l = 0; l < 64; l++) acc = fmaf(sBk[l][n], sXd[l][p], acc);
        g_S[sbase + idx] = acc;
    }
}

// ---------------- 6. sequential scan over chunks ----------------
__global__ __launch_bounds__(256) void scan_kernel()
{
    int bid = blockIdx.x;           // q + 8*(h + 32*b)
    int q = bid & 7;
    int bh = bid >> 3;
    int h = bh & 31, b = bh >> 5;
    int tid = threadIdx.x;
    int v = q * 256 + tid;
    float carry = 0.f;
    for (int c = 0; c < NC; c++) {
        int cb = ((b * NC + c) * NH + h);
        float Tc = expf(g_acs[(size_t)cb * 64 + 63]);
        size_t base = (size_t)cb * 2048;
        g_Sin[base + v] = carry;
        carry = fmaf(Tc, carry, g_S[base + v]);
    }
}

// ---------------- 7. per-chunk output ----------------
__global__ __launch_bounds__(256) void output_kernel(const float* __restrict__ Dv)
{
    int bid = blockIdx.x;           // ((b*64+c)*32+h)
    int h = bid & 31, c = (bid >> 5) & 63, b = bid >> 11;
    __shared__ float sM[64][64];
    __shared__ float sX[64][64];
    __shared__ float sCk[64][32];
    __shared__ float sAcs[64];
    __shared__ float sEA[64];
    int tid = threadIdx.x;
    int rbase = b * LEN + c * 64;
    if (tid < 64) {
        float a = g_acs[(size_t)bid * 64 + tid];
        sAcs[tid] = a;
        sEA[tid]  = expf(a);
    }
    for (int idx = tid; idx < 2048; idx += 256) {
        int l = idx >> 5, n = idx & 31;
        sCk[l][n] = g_Ccq[(rbase + l) * DST + n];
    }
    __syncthreads();
    const float* sc = g_scores + (size_t)(b * NC + c) * 4096;
    #pragma unroll 1
    for (int k = 0; k < 16; k++) {
        int idx = tid + k * 256;
        int l = idx >> 6, s_ = idx & 63;
        float m = 0.f;
        if (s_ <= l) m = sc[idx] * expf(sAcs[l] - sAcs[s_]);
        sM[l][s_] = m;
        int p = s_;
        sX[l][p] = g_xh[(size_t)(rbase + l) * DIN + h * HD + p] * g_dt[(rbase + l) * NH + h];
    }
    int p0 = tid & 63;
    float vreg[32];
    size_t sinbase = (size_t)bid * 2048 + (size_t)p0 * 32;
    #pragma unroll
    for (int n = 0; n < 32; n++) vreg[n] = g_Sin[sinbase + n];
    __syncthreads();

    int l0 = ((tid >> 4) & 15) << 2;
    int q0 = (tid & 15) << 2;
    float yd[4][4];
    #pragma unroll
    for (int i = 0; i < 4; i++)
        #pragma unroll
        for (int j = 0; j < 4; j++) yd[i][j] = 0.f;
    #pragma unroll 4
    for (int s = 0; s < 64; s++) {
        float4 xv = *reinterpret_cast<const float4*>(&sX[s][q0]);
        float xr[4] = {xv.x, xv.y, xv.z, xv.w};
        #pragma unroll
        for (int i = 0; i < 4; i++) {
            float mv = sM[l0 + i][s];
            #pragma unroll
            for (int j = 0; j < 4; j++) yd[i][j] = fmaf(mv, xr[j], yd[i][j]);
        }
    }
    __syncthreads();
    #pragma unroll
    for (int i = 0; i < 4; i++)
        #pragma unroll
        for (int j = 0; j < 4; j++) sM[l0 + i][q0 + j] = yd[i][j];
    __syncthreads();

    float Dh = Dv[h];
    #pragma unroll 1
    for (int k = 0; k < 16; k++) {
        int idx = tid + k * 256;
        int l = idx >> 6, p = idx & 63;
        float yo = 0.f;
        #pragma unroll
        for (int n = 0; n < 32; n++) yo = fmaf(sCk[l][n], vreg[n], yo);
        float xhv = g_xh[(size_t)(rbase + l) * DIN + h * HD + p];
        g_y[(size_t)(rbase + l) * DIN + h * HD + p] = sM[l][p] + sEA[l] * yo + xhv * Dh;
    }
}

// ---------------- 8. gate with silu(z) + RMSNorm ----------------
__global__ __launch_bounds__(256) void gate_kernel(const float* __restrict__ rms_w)
{
    __shared__ float sb[32];
    int r = blockIdx.x, tid = threadIdx.x;
    const float* zr = g_zx + (size_t)r * NPROJ;
    const float* yr = g_y + (size_t)r * DIN;
    float v[8]; float ss = 0.f;
    #pragma unroll
    for (int k = 0; k < 8; k++) {
        int i = tid + k * 256;
        float z = zr[i];
        float val = yr[i] * siluf(z);
        v[k] = val; ss += val * val;
    }
    ss = blk_reduce(ss, sb);
    float scale = rsqrtf(ss * (1.f / DIN) + 1e-6f);
    float* outr = g_yn + (size_t)r * DIN;
    #pragma unroll
    for (int k = 0; k < 8; k++) {
        int i = tid + k * 256;
        outr[i] = v[k] * scale * rms_w[i];
    }
}

// ---------------- launch ----------------
extern "C" void kernel_launch(void* const* d_in, const int* in_sizes, int n_in,
                              void* d_out, int out_size)
{
    const float* x       = (const float*)d_in[0];
    const float* ln_w    = (const float*)d_in[1];
    const float* ln_b    = (const float*)d_in[2];
    const float* W_in    = (const float*)d_in[3];
    const float* dt_bias = (const float*)d_in[4];
    const float* A_log   = (const float*)d_in[5];
    const float* Dv      = (const float*)d_in[6];
    const float* rms_w   = (const float*)d_in[7];
    const float* W_out   = (const float*)d_in[8];
    float* out = (float*)d_out;

    float *pH = nullptr, *pZX = nullptr, *pYN = nullptr, *pWinT = nullptr, *pWoutT = nullptr;
    cudaGetSymbolAddress((void**)&pH,  g_h);
    cudaGetSymbolAddress((void**)&pZX, g_zx);
    cudaGetSymbolAddress((void**)&pYN, g_yn);
    cudaGetSymbolAddress((void**)&pWinT, g_WinT);
    cudaGetSymbolAddress((void**)&pWoutT, g_WoutT);

    transpose_kernel<<<dim3(NPROJ / 32, DMODEL / 32), 256>>>(W_in, pWinT, DMODEL, NPROJ);
    transpose_kernel<<<dim3(DMODEL / 32, DIN / 32), 256>>>(W_out, pWoutT, DIN, DMODEL);

    layernorm_kernel<<<NROWS, 256>>>(x, ln_w, ln_b);
    mma_gemm_kernel<<<dim3((NPROJ + 127) / 128, NROWS / 128), 256>>>(
        pH, pWinT, nullptr, pZX, NROWS, NPROJ, DMODEL);
    prep_kernel<<<NROWS, 256>>>(dt_bias, A_log);
    scores_kernel<<<BSZ * NC, 256>>>();
    chunkstate_kernel<<<BSZ * NC * NH, 256>>>();
    scan_kernel<<<BSZ * NH * 8, 256>>>();
    output_kernel<<<BSZ * NC * NH, 256>>>(Dv);
    gate_kernel<<<NROWS, 256>>>(rms_w);
    mma_gemm_kernel<<<dim3(DMODEL / 128, NROWS / 128), 256>>>(
        pYN, pWoutT, x, out, NROWS, DMODEL, DIN);
}